// round 2
// baseline (speedup 1.0000x reference)
#include <cuda_runtime.h>
#include <cuda_bf16.h>
#include <cstdint>

#define NN   50000
#define EE   800000
#define HH   128
#define GG   64
#define OUTD 10

// ---------------- scratch (device globals; no dynamic allocation) ----------
__device__ float g_bufA[(size_t)NN * HH];
__device__ float g_bufB[(size_t)NN * HH];
__device__ int   g_src[EE];
__device__ int   g_dst[EE];
__device__ int   g_batch[NN];
__device__ int   g_deg[NN];
__device__ int   g_rowstart[NN + 1];
__device__ int   g_cursor[NN];
__device__ float g_dinv[NN];
__device__ int   g_csr_src[EE];
__device__ float g_csr_w[EE];
__device__ float g_pooled[GG * HH];
__device__ float g_cnts[GG];
__device__ int   g_is64;

// ---------------- dtype sniffing + normalization ---------------------------
// If the edge_index buffer holds int64 (nonneg values < 2^31), every odd
// 32-bit word is 0. If it holds int32, odd words are random node indices.
__global__ void k_detect(const int* __restrict__ p) {
    __shared__ int any;
    if (threadIdx.x == 0) any = 0;
    __syncthreads();
    int v = 0;
    for (int i = threadIdx.x; i < 4096; i += blockDim.x) v |= p[2 * i + 1];
    if (v) atomicOr(&any, 1);
    __syncthreads();
    if (threadIdx.x == 0) g_is64 = any ? 0 : 1;
}

__global__ void k_cvt_edges(const void* __restrict__ p) {
    int e = blockIdx.x * blockDim.x + threadIdx.x;
    if (e >= EE) return;
    int s, d;
    if (g_is64) {
        const long long* q = (const long long*)p;
        s = (int)q[e];
        d = (int)q[EE + e];
    } else {
        const int* q = (const int*)p;
        s = q[e];
        d = q[EE + e];
    }
    // defensive clamp: never let a bad index turn into an IMA
    s = min(max(s, 0), NN - 1);
    d = min(max(d, 0), NN - 1);
    g_src[e] = s;
    g_dst[e] = d;
}

__global__ void k_cvt_batch(const void* __restrict__ p) {
    int n = blockIdx.x * blockDim.x + threadIdx.x;
    if (n >= NN) return;
    int b;
    if (g_is64) b = (int)((const long long*)p)[n];
    else        b = ((const int*)p)[n];
    g_batch[n] = min(max(b, 0), GG - 1);
}

// ---------------- setup kernels --------------------------------------------
__global__ void k_zero() {
    int i = blockIdx.x * blockDim.x + threadIdx.x;
    if (i < NN) g_deg[i] = 0;
    if (i < GG * HH) g_pooled[i] = 0.0f;
    if (i < GG) g_cnts[i] = 0.0f;
}

__global__ void k_hist() {
    int e = blockIdx.x * blockDim.x + threadIdx.x;
    if (e < EE) atomicAdd(&g_deg[g_dst[e]], 1);
}

// single-block exclusive scan of g_deg -> g_rowstart (N+1 entries)
__global__ void k_scan() {
    __shared__ int part[1024];
    const int CHUNK = 49;                 // 1024*49 = 50176 >= 50001
    int t = threadIdx.x;
    int base = t * CHUNK;
    int s = 0;
    for (int i = 0; i < CHUNK; i++) {
        int idx = base + i;
        if (idx < NN) s += g_deg[idx];
    }
    part[t] = s;
    __syncthreads();
    for (int off = 1; off < 1024; off <<= 1) {
        int v = (t >= off) ? part[t - off] : 0;
        __syncthreads();
        part[t] += v;
        __syncthreads();
    }
    int run = (t == 0) ? 0 : part[t - 1];
    for (int i = 0; i < CHUNK; i++) {
        int idx = base + i;
        if (idx <= NN) {
            g_rowstart[idx] = run;
            if (idx < NN) run += g_deg[idx];
        }
    }
}

__global__ void k_prep() {
    int n = blockIdx.x * blockDim.x + threadIdx.x;
    if (n < NN) {
        g_dinv[n] = rsqrtf((float)g_deg[n] + 1.0f);
        g_cursor[n] = g_rowstart[n];
    }
}

__global__ void k_fill() {
    int e = blockIdx.x * blockDim.x + threadIdx.x;
    if (e < EE) {
        int s = g_src[e];
        int d = g_dst[e];
        float w = g_dinv[s] * g_dinv[d];
        int pos = atomicAdd(&g_cursor[d], 1);
        g_csr_src[pos] = s;
        g_csr_w[pos]   = w;
    }
}

// ---------------- GEMM: C[N,128] = act(A)[N,128] @ W[128,128] --------------
// BM=128, BN=128, BK=32; 256 threads, each computes 8x8 via packed f32x2 FMA.
__global__ void __launch_bounds__(256) k_gemm(const float* __restrict__ A,
                                              const float* __restrict__ W,
                                              float* __restrict__ C,
                                              int nRows, int doRelu) {
    __shared__ __align__(16) float Ask[32][132];   // transposed A slab (padded)
    __shared__ __align__(16) float Ws[32][128];

    int tid = threadIdx.x;
    int tx = tid & 15;        // 16 col-groups of 8
    int ty = tid >> 4;        // 16 row-groups of 8
    int row0 = blockIdx.x * 128;

    unsigned long long acc[8][4];
#pragma unroll
    for (int i = 0; i < 8; i++)
#pragma unroll
        for (int j = 0; j < 4; j++) acc[i][j] = 0ull;

    for (int kb = 0; kb < 128; kb += 32) {
#pragma unroll
        for (int i = 0; i < 4; i++) {
            int idx = tid + i * 256;      // float4 index, 0..1023
            int r  = idx >> 3;            // row 0..127
            int c4 = idx & 7;             // float4 within 32 cols
            float4 v = make_float4(0.f, 0.f, 0.f, 0.f);
            if (row0 + r < nRows)
                v = *(const float4*)(A + (size_t)(row0 + r) * 128 + kb + c4 * 4);
            if (doRelu) {
                v.x = fmaxf(v.x, 0.f); v.y = fmaxf(v.y, 0.f);
                v.z = fmaxf(v.z, 0.f); v.w = fmaxf(v.w, 0.f);
            }
            Ask[c4 * 4 + 0][r] = v.x;
            Ask[c4 * 4 + 1][r] = v.y;
            Ask[c4 * 4 + 2][r] = v.z;
            Ask[c4 * 4 + 3][r] = v.w;
        }
#pragma unroll
        for (int i = 0; i < 4; i++) {
            int idx = tid + i * 256;
            int r  = idx >> 5;
            int c4 = idx & 31;
            *(float4*)&Ws[r][c4 * 4] = *(const float4*)(W + (size_t)(kb + r) * 128 + c4 * 4);
        }
        __syncthreads();

#pragma unroll
        for (int k = 0; k < 32; k++) {
            float4 a0 = *(float4*)&Ask[k][ty * 8];
            float4 a1 = *(float4*)&Ask[k][ty * 8 + 4];
            ulonglong2 b01 = *(ulonglong2*)&Ws[k][tx * 8];
            ulonglong2 b23 = *(ulonglong2*)&Ws[k][tx * 8 + 4];
            float ar[8] = {a0.x, a0.y, a0.z, a0.w, a1.x, a1.y, a1.z, a1.w};
            unsigned long long bp[4] = {b01.x, b01.y, b23.x, b23.y};
#pragma unroll
            for (int i = 0; i < 8; i++) {
                unsigned long long a2;
                unsigned int ab = __float_as_uint(ar[i]);
                asm("mov.b64 %0, {%1,%1};" : "=l"(a2) : "r"(ab));
#pragma unroll
                for (int j = 0; j < 4; j++)
                    asm("fma.rn.f32x2 %0, %1, %2, %0;"
                        : "+l"(acc[i][j]) : "l"(a2), "l"(bp[j]));
            }
        }
        __syncthreads();
    }

#pragma unroll
    for (int i = 0; i < 8; i++) {
        int r = row0 + ty * 8 + i;
        if (r < nRows) {
            float o[8];
#pragma unroll
            for (int j = 0; j < 4; j++) {
                unsigned int lo, hi;
                asm("mov.b64 {%0,%1}, %2;" : "=r"(lo), "=r"(hi) : "l"(acc[i][j]));
                o[2 * j]     = __uint_as_float(lo);
                o[2 * j + 1] = __uint_as_float(hi);
            }
            *(float4*)&C[(size_t)r * 128 + tx * 8]     = make_float4(o[0], o[1], o[2], o[3]);
            *(float4*)&C[(size_t)r * 128 + tx * 8 + 4] = make_float4(o[4], o[5], o[6], o[7]);
        }
    }
}

// ---------------- CSR gather aggregation -----------------------------------
// warp per node: out[n] = dinv[n]^2 * h[n] + sum_{e in CSR[n]} w_e * h[src_e]
__global__ void __launch_bounds__(256) k_gather(const float* __restrict__ h,
                                                float* __restrict__ out) {
    int warp = (blockIdx.x * blockDim.x + threadIdx.x) >> 5;
    int lane = threadIdx.x & 31;
    if (warp >= NN) return;
    int n = warp;

    const float4* h4 = (const float4*)h;
    float di = g_dinv[n];
    float sw = di * di;
    float4 hv = h4[(size_t)n * 32 + lane];
    float4 acc = make_float4(hv.x * sw, hv.y * sw, hv.z * sw, hv.w * sw);

    int i   = g_rowstart[n];
    int end = g_rowstart[n + 1];
    for (; i + 1 < end; i += 2) {
        int s0 = g_csr_src[i];
        int s1 = g_csr_src[i + 1];
        float w0 = g_csr_w[i];
        float w1 = g_csr_w[i + 1];
        float4 v0 = h4[(size_t)s0 * 32 + lane];
        float4 v1 = h4[(size_t)s1 * 32 + lane];
        acc.x += w0 * v0.x + w1 * v1.x;
        acc.y += w0 * v0.y + w1 * v1.y;
        acc.z += w0 * v0.z + w1 * v1.z;
        acc.w += w0 * v0.w + w1 * v1.w;
    }
    if (i < end) {
        int s0 = g_csr_src[i];
        float w0 = g_csr_w[i];
        float4 v0 = h4[(size_t)s0 * 32 + lane];
        acc.x += w0 * v0.x; acc.y += w0 * v0.y;
        acc.z += w0 * v0.z; acc.w += w0 * v0.w;
    }
    ((float4*)out)[(size_t)n * 32 + lane] = acc;
}

// ---------------- pooling ---------------------------------------------------
__global__ void k_cnt() {
    int n = blockIdx.x * blockDim.x + threadIdx.x;
    if (n < NN) atomicAdd(&g_cnts[g_batch[n]], 1.0f);
}

// thread = feature dim; block handles 256 sorted nodes, flushing on graph change
__global__ void __launch_bounds__(128) k_pool(const float* __restrict__ h) {
    int d = threadIdx.x;                  // 0..127
    int n0 = blockIdx.x * 256;
    int n1 = n0 + 256; if (n1 > NN) n1 = NN;
    if (n0 >= NN) return;
    float acc = 0.0f;
    int g = g_batch[n0];
    for (int n = n0; n < n1; n++) {
        int b = g_batch[n];
        if (b != g) {
            atomicAdd(&g_pooled[g * HH + d], acc);
            acc = 0.0f;
            g = b;
        }
        acc += h[(size_t)n * HH + d];
    }
    atomicAdd(&g_pooled[g * HH + d], acc);
}

// ---------------- final MLP (single block) ----------------------------------
__global__ void __launch_bounds__(256) k_mlp(const float* __restrict__ M0w,
                                             const float* __restrict__ M0b,
                                             const float* __restrict__ M1w,
                                             const float* __restrict__ M1b,
                                             float* __restrict__ out) {
    __shared__ float pv[GG * HH];         // 32KB
    int t = threadIdx.x;
    for (int i = t; i < GG * HH; i += 256) {
        int g = i >> 7;
        pv[i] = g_pooled[i] / fmaxf(g_cnts[g], 1.0f);
    }
    __syncthreads();
    float hid[32];
#pragma unroll
    for (int i = 0; i < 32; i++) {
        int idx = t + 256 * i;
        int g = idx >> 7, j = idx & 127;
        float s = M0b[j];
        for (int k = 0; k < 128; k++) s += pv[(g << 7) + k] * M0w[k * 128 + j];
        hid[i] = fmaxf(s, 0.0f);
    }
    __syncthreads();
#pragma unroll
    for (int i = 0; i < 32; i++) pv[t + 256 * i] = hid[i];
    __syncthreads();
    for (int o = t; o < GG * OUTD; o += 256) {
        int g = o / OUTD, c = o % OUTD;
        float s = M1b[c];
        for (int j = 0; j < 128; j++) s += pv[(g << 7) + j] * M1w[j * OUTD + c];
        out[o] = s;
    }
}

// ---------------- launch ----------------------------------------------------
extern "C" void kernel_launch(void* const* d_in, const int* in_sizes, int n_in,
                              void* d_out, int out_size) {
    const float* x   = (const float*)d_in[0];
    const float* W0  = (const float*)d_in[1];
    const float* W1  = (const float*)d_in[2];
    const float* W2  = (const float*)d_in[3];
    const float* M0w = (const float*)d_in[4];
    const float* M0b = (const float*)d_in[5];
    const float* M1w = (const float*)d_in[6];
    const float* M1b = (const float*)d_in[7];
    const void*  ei  = d_in[8];
    const void*  bat = d_in[9];
    float* out = (float*)d_out;

    float* bufA = nullptr;
    float* bufB = nullptr;
    cudaGetSymbolAddress((void**)&bufA, g_bufA);
    cudaGetSymbolAddress((void**)&bufB, g_bufB);

    const int T = 256;
    int gN = (NN + T - 1) / T;            // 196
    int gE = (EE + T - 1) / T;            // 3125
    int gGemm   = (NN + 127) / 128;       // 391
    int gGather = (NN * 32 + T - 1) / T;  // 6250

    // dtype sniff + normalize indices to int32 scratch
    k_detect<<<1, 256>>>((const int*)ei);
    k_cvt_edges<<<gE, T>>>(ei);
    k_cvt_batch<<<gN, T>>>(bat);

    // CSR build (reused for all 3 layers)
    k_zero<<<gN, T>>>();
    k_hist<<<gE, T>>>();
    k_scan<<<1, 1024>>>();
    k_prep<<<gN, T>>>();
    k_fill<<<gE, T>>>();

    // layer 1
    k_gemm<<<gGemm, T>>>(x, W0, bufA, NN, 0);
    k_gather<<<gGather, T>>>(bufA, bufB);
    // layer 2
    k_gemm<<<gGemm, T>>>(bufB, W1, bufA, NN, 1);
    k_gather<<<gGather, T>>>(bufA, bufB);
    // layer 3
    k_gemm<<<gGemm, T>>>(bufB, W2, bufA, NN, 1);
    k_gather<<<gGather, T>>>(bufA, bufB);

    // pooling + MLP
    k_cnt<<<gN, T>>>();
    k_pool<<<(NN + 255) / 256, 128>>>(bufB);
    k_mlp<<<1, 256>>>(M0w, M0b, M1w, M1b, out);
}

// round 3
// speedup vs baseline: 1.1314x; 1.1314x over previous
#include <cuda_runtime.h>
#include <cuda_fp16.h>
#include <cstdint>

#define NN   50000
#define EE   800000
#define HH   128
#define GG   64
#define OUTD 10

// ---------------- scratch (device globals; no dynamic allocation) ----------
__device__ float  g_bufF[(size_t)NN * HH];   // fp32 gather output / gemm input
__device__ __half g_h16[(size_t)NN * HH];    // fp16 gemm output / gather input
__device__ int    g_src[EE];
__device__ int    g_dst[EE];
__device__ int    g_batch[NN];
__device__ int    g_deg[NN];
__device__ int    g_rowstart[NN + 1];
__device__ int    g_cursor[NN];
__device__ float  g_dinv[NN];
__device__ int2   g_csr[EE];                 // packed (src, w-as-int)
__device__ float  g_pooled[GG * HH];
__device__ float  g_cnts[GG];
__device__ int    g_is64;

// ---------------- dtype sniffing + normalization ---------------------------
__global__ void k_detect(const int* __restrict__ p) {
    __shared__ int any;
    if (threadIdx.x == 0) any = 0;
    __syncthreads();
    int v = 0;
    for (int i = threadIdx.x; i < 4096; i += blockDim.x) v |= p[2 * i + 1];
    if (v) atomicOr(&any, 1);
    __syncthreads();
    if (threadIdx.x == 0) g_is64 = any ? 0 : 1;
}

__global__ void k_cvt_edges(const void* __restrict__ p) {
    int e = blockIdx.x * blockDim.x + threadIdx.x;
    if (e >= EE) return;
    int s, d;
    if (g_is64) {
        const long long* q = (const long long*)p;
        s = (int)q[e];
        d = (int)q[EE + e];
    } else {
        const int* q = (const int*)p;
        s = q[e];
        d = q[EE + e];
    }
    s = min(max(s, 0), NN - 1);
    d = min(max(d, 0), NN - 1);
    g_src[e] = s;
    g_dst[e] = d;
}

__global__ void k_cvt_batch(const void* __restrict__ p) {
    int n = blockIdx.x * blockDim.x + threadIdx.x;
    if (n >= NN) return;
    int b;
    if (g_is64) b = (int)((const long long*)p)[n];
    else        b = ((const int*)p)[n];
    g_batch[n] = min(max(b, 0), GG - 1);
}

// ---------------- setup kernels --------------------------------------------
__global__ void k_zero() {
    int i = blockIdx.x * blockDim.x + threadIdx.x;
    if (i < NN) g_deg[i] = 0;
    if (i < GG * HH) g_pooled[i] = 0.0f;
    if (i < GG) g_cnts[i] = 0.0f;
}

__global__ void k_hist() {
    int e = blockIdx.x * blockDim.x + threadIdx.x;
    if (e < EE) atomicAdd(&g_deg[g_dst[e]], 1);
}

// single-block exclusive scan of g_deg -> g_rowstart (N+1 entries)
__global__ void k_scan() {
    __shared__ int part[1024];
    const int CHUNK = 49;                 // 1024*49 = 50176 >= 50001
    int t = threadIdx.x;
    int base = t * CHUNK;
    int s = 0;
    for (int i = 0; i < CHUNK; i++) {
        int idx = base + i;
        if (idx < NN) s += g_deg[idx];
    }
    part[t] = s;
    __syncthreads();
    for (int off = 1; off < 1024; off <<= 1) {
        int v = (t >= off) ? part[t - off] : 0;
        __syncthreads();
        part[t] += v;
        __syncthreads();
    }
    int run = (t == 0) ? 0 : part[t - 1];
    for (int i = 0; i < CHUNK; i++) {
        int idx = base + i;
        if (idx <= NN) {
            g_rowstart[idx] = run;
            if (idx < NN) run += g_deg[idx];
        }
    }
}

__global__ void k_prep() {
    int n = blockIdx.x * blockDim.x + threadIdx.x;
    if (n < NN) {
        g_dinv[n] = rsqrtf((float)g_deg[n] + 1.0f);
        g_cursor[n] = g_rowstart[n];
    }
}

__global__ void k_fill() {
    int e = blockIdx.x * blockDim.x + threadIdx.x;
    if (e < EE) {
        int s = g_src[e];
        int d = g_dst[e];
        float w = g_dinv[s] * g_dinv[d];
        int pos = atomicAdd(&g_cursor[d], 1);
        g_csr[pos] = make_int2(s, __float_as_int(w));
    }
}

// ---------------- GEMM: C[N,128](fp16) = act(A)[N,128] @ W[128,128] --------
__global__ void __launch_bounds__(256) k_gemm(const float* __restrict__ A,
                                              const float* __restrict__ W,
                                              __half* __restrict__ C,
                                              int nRows, int doRelu) {
    __shared__ __align__(16) float Ask[32][132];   // transposed A slab (padded)
    __shared__ __align__(16) float Ws[32][128];

    int tid = threadIdx.x;
    int tx = tid & 15;        // 16 col-groups of 8
    int ty = tid >> 4;        // 16 row-groups of 8
    int row0 = blockIdx.x * 128;

    unsigned long long acc[8][4];
#pragma unroll
    for (int i = 0; i < 8; i++)
#pragma unroll
        for (int j = 0; j < 4; j++) acc[i][j] = 0ull;

    for (int kb = 0; kb < 128; kb += 32) {
#pragma unroll
        for (int i = 0; i < 4; i++) {
            int idx = tid + i * 256;      // float4 index, 0..1023
            int r  = idx >> 3;            // row 0..127
            int c4 = idx & 7;             // float4 within 32 cols
            float4 v = make_float4(0.f, 0.f, 0.f, 0.f);
            if (row0 + r < nRows)
                v = *(const float4*)(A + (size_t)(row0 + r) * 128 + kb + c4 * 4);
            if (doRelu) {
                v.x = fmaxf(v.x, 0.f); v.y = fmaxf(v.y, 0.f);
                v.z = fmaxf(v.z, 0.f); v.w = fmaxf(v.w, 0.f);
            }
            Ask[c4 * 4 + 0][r] = v.x;
            Ask[c4 * 4 + 1][r] = v.y;
            Ask[c4 * 4 + 2][r] = v.z;
            Ask[c4 * 4 + 3][r] = v.w;
        }
#pragma unroll
        for (int i = 0; i < 4; i++) {
            int idx = tid + i * 256;
            int r  = idx >> 5;
            int c4 = idx & 31;
            *(float4*)&Ws[r][c4 * 4] = *(const float4*)(W + (size_t)(kb + r) * 128 + c4 * 4);
        }
        __syncthreads();

#pragma unroll
        for (int k = 0; k < 32; k++) {
            float4 a0 = *(float4*)&Ask[k][ty * 8];
            float4 a1 = *(float4*)&Ask[k][ty * 8 + 4];
            ulonglong2 b01 = *(ulonglong2*)&Ws[k][tx * 8];
            ulonglong2 b23 = *(ulonglong2*)&Ws[k][tx * 8 + 4];
            float ar[8] = {a0.x, a0.y, a0.z, a0.w, a1.x, a1.y, a1.z, a1.w};
            unsigned long long bp[4] = {b01.x, b01.y, b23.x, b23.y};
#pragma unroll
            for (int i = 0; i < 8; i++) {
                unsigned long long a2;
                unsigned int ab = __float_as_uint(ar[i]);
                asm("mov.b64 %0, {%1,%1};" : "=l"(a2) : "r"(ab));
#pragma unroll
                for (int j = 0; j < 4; j++)
                    asm("fma.rn.f32x2 %0, %1, %2, %0;"
                        : "+l"(acc[i][j]) : "l"(a2), "l"(bp[j]));
            }
        }
        __syncthreads();
    }

#pragma unroll
    for (int i = 0; i < 8; i++) {
        int r = row0 + ty * 8 + i;
        if (r < nRows) {
            float o[8];
#pragma unroll
            for (int j = 0; j < 4; j++) {
                unsigned int lo, hi;
                asm("mov.b64 {%0,%1}, %2;" : "=r"(lo), "=r"(hi) : "l"(acc[i][j]));
                o[2 * j]     = __uint_as_float(lo);
                o[2 * j + 1] = __uint_as_float(hi);
            }
            __half2 p0 = __floats2half2_rn(o[0], o[1]);
            __half2 p1 = __floats2half2_rn(o[2], o[3]);
            __half2 p2 = __floats2half2_rn(o[4], o[5]);
            __half2 p3 = __floats2half2_rn(o[6], o[7]);
            uint4 pv;
            pv.x = *(unsigned int*)&p0;
            pv.y = *(unsigned int*)&p1;
            pv.z = *(unsigned int*)&p2;
            pv.w = *(unsigned int*)&p3;
            *(uint4*)&C[(size_t)r * 128 + tx * 8] = pv;
        }
    }
}

// ---------------- CSR gather aggregation (fp16 in, fp32 out) ----------------
// warp per node: out[n] = dinv[n]^2 * h[n] + sum_{e in CSR[n]} w_e * h[src_e]
// each lane owns 4 feature dims -> one 8B load (4 halves) per row.
__device__ __forceinline__ float4 h4conv(uint2 v) {
    __half2 a = *(__half2*)&v.x;
    __half2 b = *(__half2*)&v.y;
    float2 fa = __half22float2(a);
    float2 fb = __half22float2(b);
    return make_float4(fa.x, fa.y, fb.x, fb.y);
}

__global__ void __launch_bounds__(256) k_gather(const __half* __restrict__ h,
                                                float* __restrict__ out) {
    int warp = (blockIdx.x * blockDim.x + threadIdx.x) >> 5;
    int lane = threadIdx.x & 31;
    if (warp >= NN) return;
    int n = warp;

    const uint2* h2 = (const uint2*)h;   // 32 uint2 per 128-half row
    float di = g_dinv[n];
    float sw = di * di;
    float4 hv = h4conv(h2[(size_t)n * 32 + lane]);
    float4 acc = make_float4(hv.x * sw, hv.y * sw, hv.z * sw, hv.w * sw);

    int i   = g_rowstart[n];
    int end = g_rowstart[n + 1];
    for (; i + 3 < end; i += 4) {
        int2 e0 = g_csr[i], e1 = g_csr[i + 1], e2 = g_csr[i + 2], e3 = g_csr[i + 3];
        float4 v0 = h4conv(h2[(size_t)e0.x * 32 + lane]);
        float4 v1 = h4conv(h2[(size_t)e1.x * 32 + lane]);
        float4 v2 = h4conv(h2[(size_t)e2.x * 32 + lane]);
        float4 v3 = h4conv(h2[(size_t)e3.x * 32 + lane]);
        float w0 = __int_as_float(e0.y), w1 = __int_as_float(e1.y);
        float w2 = __int_as_float(e2.y), w3 = __int_as_float(e3.y);
        acc.x += w0 * v0.x + w1 * v1.x + w2 * v2.x + w3 * v3.x;
        acc.y += w0 * v0.y + w1 * v1.y + w2 * v2.y + w3 * v3.y;
        acc.z += w0 * v0.z + w1 * v1.z + w2 * v2.z + w3 * v3.z;
        acc.w += w0 * v0.w + w1 * v1.w + w2 * v2.w + w3 * v3.w;
    }
    for (; i < end; i++) {
        int2 e0 = g_csr[i];
        float w0 = __int_as_float(e0.y);
        float4 v0 = h4conv(h2[(size_t)e0.x * 32 + lane]);
        acc.x += w0 * v0.x; acc.y += w0 * v0.y;
        acc.z += w0 * v0.z; acc.w += w0 * v0.w;
    }
    ((float4*)out)[(size_t)n * 32 + lane] = acc;
}

// ---------------- pooling ---------------------------------------------------
__global__ void k_cnt() {
    int n = blockIdx.x * blockDim.x + threadIdx.x;
    if (n < NN) atomicAdd(&g_cnts[g_batch[n]], 1.0f);
}

__global__ void __launch_bounds__(128) k_pool(const float* __restrict__ h) {
    int d = threadIdx.x;                  // 0..127
    int n0 = blockIdx.x * 256;
    int n1 = n0 + 256; if (n1 > NN) n1 = NN;
    if (n0 >= NN) return;
    float acc = 0.0f;
    int g = g_batch[n0];
    for (int n = n0; n < n1; n++) {
        int b = g_batch[n];
        if (b != g) {
            atomicAdd(&g_pooled[g * HH + d], acc);
            acc = 0.0f;
            g = b;
        }
        acc += h[(size_t)n * HH + d];
    }
    atomicAdd(&g_pooled[g * HH + d], acc);
}

// ---------------- final MLP (single block) ----------------------------------
__global__ void __launch_bounds__(256) k_mlp(const float* __restrict__ M0w,
                                             const float* __restrict__ M0b,
                                             const float* __restrict__ M1w,
                                             const float* __restrict__ M1b,
                                             float* __restrict__ out) {
    __shared__ float pv[GG * HH];         // 32KB
    int t = threadIdx.x;
    for (int i = t; i < GG * HH; i += 256) {
        int g = i >> 7;
        pv[i] = g_pooled[i] / fmaxf(g_cnts[g], 1.0f);
    }
    __syncthreads();
    float hid[32];
#pragma unroll
    for (int i = 0; i < 32; i++) {
        int idx = t + 256 * i;
        int g = idx >> 7, j = idx & 127;
        float s = M0b[j];
        for (int k = 0; k < 128; k++) s += pv[(g << 7) + k] * M0w[k * 128 + j];
        hid[i] = fmaxf(s, 0.0f);
    }
    __syncthreads();
#pragma unroll
    for (int i = 0; i < 32; i++) pv[t + 256 * i] = hid[i];
    __syncthreads();
    for (int o = t; o < GG * OUTD; o += 256) {
        int g = o / OUTD, c = o % OUTD;
        float s = M1b[c];
        for (int j = 0; j < 128; j++) s += pv[(g << 7) + j] * M1w[j * OUTD + c];
        out[o] = s;
    }
}

// ---------------- launch ----------------------------------------------------
extern "C" void kernel_launch(void* const* d_in, const int* in_sizes, int n_in,
                              void* d_out, int out_size) {
    const float* x   = (const float*)d_in[0];
    const float* W0  = (const float*)d_in[1];
    const float* W1  = (const float*)d_in[2];
    const float* W2  = (const float*)d_in[3];
    const float* M0w = (const float*)d_in[4];
    const float* M0b = (const float*)d_in[5];
    const float* M1w = (const float*)d_in[6];
    const float* M1b = (const float*)d_in[7];
    const void*  ei  = d_in[8];
    const void*  bat = d_in[9];
    float* out = (float*)d_out;

    float*  bufF = nullptr;
    __half* h16  = nullptr;
    cudaGetSymbolAddress((void**)&bufF, g_bufF);
    cudaGetSymbolAddress((void**)&h16,  g_h16);

    const int T = 256;
    int gN = (NN + T - 1) / T;            // 196
    int gE = (EE + T - 1) / T;            // 3125
    int gGemm   = (NN + 127) / 128;       // 391
    int gGather = (NN * 32 + T - 1) / T;  // 6250

    // dtype sniff + normalize indices to int32 scratch
    k_detect<<<1, 256>>>((const int*)ei);
    k_cvt_edges<<<gE, T>>>(ei);
    k_cvt_batch<<<gN, T>>>(bat);

    // CSR build (reused for all 3 layers)
    k_zero<<<gN, T>>>();
    k_hist<<<gE, T>>>();
    k_scan<<<1, 1024>>>();
    k_prep<<<gN, T>>>();
    k_fill<<<gE, T>>>();

    // layer 1
    k_gemm<<<gGemm, T>>>(x, W0, h16, NN, 0);
    k_gather<<<gGather, T>>>(h16, bufF);
    // layer 2
    k_gemm<<<gGemm, T>>>(bufF, W1, h16, NN, 1);
    k_gather<<<gGather, T>>>(h16, bufF);
    // layer 3
    k_gemm<<<gGemm, T>>>(bufF, W2, h16, NN, 1);
    k_gather<<<gGather, T>>>(h16, bufF);

    // pooling + MLP
    k_cnt<<<gN, T>>>();
    k_pool<<<(NN + 255) / 256, 128>>>(bufF);
    k_mlp<<<1, 256>>>(M0w, M0b, M1w, M1b, out);
}